// round 1
// baseline (speedup 1.0000x reference)
#include <cuda_runtime.h>
#include <math.h>

#define BB 8
#define CC 256
#define HH_ 64
#define WW_ 64
#define NN 4096   // H*W
#define MM 1024   // pooled
#define DD 32     // C/8
#define DV 128    // C/2

// ---------------- scratch (static device globals; allocation-free) ----------------
__device__ float g_Q[BB * NN * DD];   // [b][p][dd]       16 MB
__device__ float g_K[BB * MM * DD];   // [b][mp][dd]       1 MB
__device__ float g_V[BB * MM * DV];   // [b][mp][v]        4 MB
__device__ float g_E[BB * NN * MM];   // exp(scores)     128 MB
__device__ float g_S[BB * NN];        // row sums
__device__ float g_O[BB * NN * DV];   // [b][p][v]        16 MB

// ---------------- K1: Q projection  q[b,p,dd] = sum_c Wq[dd,c] x[b,c,p] ----------------
__global__ __launch_bounds__(256) void k_proj_q(const float* __restrict__ x,
                                                const float* __restrict__ Wq) {
    __shared__ __align__(16) float wt[CC * DD];  // transposed: [c][dd]
    int b = blockIdx.x, pt = blockIdx.y, tid = threadIdx.x;
    for (int i = tid; i < DD * CC; i += 256) {
        int dd = i >> 8, c = i & 255;
        wt[c * DD + dd] = Wq[i];
    }
    __syncthreads();
    int p = pt * 256 + tid;
    const float* xp = x + (size_t)b * CC * NN + p;
    float acc[DD];
#pragma unroll
    for (int i = 0; i < DD; ++i) acc[i] = 0.f;
#pragma unroll 4
    for (int c = 0; c < CC; ++c) {
        float xv = xp[(size_t)c * NN];
        const float4* w4 = (const float4*)(wt + c * DD);
#pragma unroll
        for (int j = 0; j < 8; ++j) {
            float4 w = w4[j];
            acc[4 * j + 0] += w.x * xv;
            acc[4 * j + 1] += w.y * xv;
            acc[4 * j + 2] += w.z * xv;
            acc[4 * j + 3] += w.w * xv;
        }
    }
    float4* qo = (float4*)(g_Q + ((size_t)b * NN + p) * DD);
#pragma unroll
    for (int j = 0; j < 8; ++j)
        qo[j] = make_float4(acc[4 * j], acc[4 * j + 1], acc[4 * j + 2], acc[4 * j + 3]);
}

// ---------------- K2: pooled K/V projections (max over 2x2) ----------------
// gridDim.z = 5 row-groups: g==0 -> Wk rows 0..31 (K), g=1..4 -> Wv rows (g-1)*32..
__global__ __launch_bounds__(256) void k_proj_kv(const float* __restrict__ x,
                                                 const float* __restrict__ Wk,
                                                 const float* __restrict__ Wv) {
    __shared__ __align__(16) float wt[CC * DD];  // [c][dd]
    int b = blockIdx.x, mt = blockIdx.y, g = blockIdx.z, tid = threadIdx.x;
    const float* Wsrc = (g == 0) ? Wk : (Wv + (size_t)(g - 1) * DD * CC);
    for (int i = tid; i < DD * CC; i += 256) {
        int dd = i >> 8, c = i & 255;
        wt[c * DD + dd] = Wsrc[i];
    }
    __syncthreads();
    int mp = mt * 256 + tid;
    int hh = mp >> 5, ww = mp & 31;
    const float* xb = x + (size_t)b * CC * NN;
    float acc[DD];
#pragma unroll
    for (int i = 0; i < DD; ++i) acc[i] = -3.4e38f;
    for (int j = 0; j < 4; ++j) {
        int p = (hh * 2 + (j >> 1)) * WW_ + ww * 2 + (j & 1);
        float s[DD];
#pragma unroll
        for (int i = 0; i < DD; ++i) s[i] = 0.f;
#pragma unroll 2
        for (int c = 0; c < CC; ++c) {
            float xv = xb[(size_t)c * NN + p];
            const float4* w4 = (const float4*)(wt + c * DD);
#pragma unroll
            for (int jj = 0; jj < 8; ++jj) {
                float4 w = w4[jj];
                s[4 * jj + 0] += w.x * xv;
                s[4 * jj + 1] += w.y * xv;
                s[4 * jj + 2] += w.z * xv;
                s[4 * jj + 3] += w.w * xv;
            }
        }
#pragma unroll
        for (int i = 0; i < DD; ++i) acc[i] = fmaxf(acc[i], s[i]);
    }
    float* dst = (g == 0) ? (g_K + ((size_t)b * MM + mp) * DD)
                          : (g_V + ((size_t)b * MM + mp) * DV + (g - 1) * DD);
    float4* d4 = (float4*)dst;
#pragma unroll
    for (int j = 0; j < 8; ++j)
        d4[j] = make_float4(acc[4 * j], acc[4 * j + 1], acc[4 * j + 2], acc[4 * j + 3]);
}

// ---------------- K3: scores + exp + row sums ----------------
// CTA = (b, tile of 64 queries). Each warp handles 4 queries per pass (q in regs),
// lanes sweep m. Writes E = exp(q.k), S = row sums (normalization deferred to K4).
__global__ __launch_bounds__(256) void k_attn() {
    __shared__ __align__(16) float ksh[DD * 129];  // transposed K chunk [c][m_local]
    int b = blockIdx.x, qt = blockIdx.y, tid = threadIdx.x;
    int warp = tid >> 5, lane = tid & 31;
    for (int pass = 0; pass < 2; ++pass) {
        int q0 = qt * 64 + pass * 32 + warp * 4;
        float qr[4][DD];
#pragma unroll
        for (int qq = 0; qq < 4; ++qq) {
            const float4* qp = (const float4*)(g_Q + ((size_t)b * NN + q0 + qq) * DD);
#pragma unroll
            for (int j = 0; j < 8; ++j) {
                float4 v = qp[j];
                qr[qq][4 * j + 0] = v.x;
                qr[qq][4 * j + 1] = v.y;
                qr[qq][4 * j + 2] = v.z;
                qr[qq][4 * j + 3] = v.w;
            }
        }
        float sum0 = 0.f, sum1 = 0.f, sum2 = 0.f, sum3 = 0.f;
        size_t e0 = ((size_t)b * NN + q0) * MM;
        for (int mc = 0; mc < 8; ++mc) {
            __syncthreads();
            const float4* src = (const float4*)(g_K + ((size_t)b * MM + mc * 128) * DD);
#pragma unroll
            for (int r = 0; r < 4; ++r) {
                int fi = r * 256 + tid;
                float4 v = src[fi];
                int ml = fi >> 3, c0 = (fi & 7) * 4;
                ksh[(c0 + 0) * 129 + ml] = v.x;
                ksh[(c0 + 1) * 129 + ml] = v.y;
                ksh[(c0 + 2) * 129 + ml] = v.z;
                ksh[(c0 + 3) * 129 + ml] = v.w;
            }
            __syncthreads();
#pragma unroll
            for (int mi = 0; mi < 4; ++mi) {
                int ml = mi * 32 + lane;
                float s0 = 0.f, s1 = 0.f, s2 = 0.f, s3 = 0.f;
#pragma unroll
                for (int c = 0; c < DD; ++c) {
                    float kv = ksh[c * 129 + ml];
                    s0 += qr[0][c] * kv;
                    s1 += qr[1][c] * kv;
                    s2 += qr[2][c] * kv;
                    s3 += qr[3][c] * kv;
                }
                float v0 = __expf(s0), v1 = __expf(s1), v2 = __expf(s2), v3 = __expf(s3);
                sum0 += v0; sum1 += v1; sum2 += v2; sum3 += v3;
                int mg = mc * 128 + ml;
                g_E[e0 + mg] = v0;
                g_E[e0 + (size_t)MM + mg] = v1;
                g_E[e0 + (size_t)2 * MM + mg] = v2;
                g_E[e0 + (size_t)3 * MM + mg] = v3;
            }
        }
#pragma unroll
        for (int o = 16; o > 0; o >>= 1) {
            sum0 += __shfl_xor_sync(0xffffffffu, sum0, o);
            sum1 += __shfl_xor_sync(0xffffffffu, sum1, o);
            sum2 += __shfl_xor_sync(0xffffffffu, sum2, o);
            sum3 += __shfl_xor_sync(0xffffffffu, sum3, o);
        }
        if (lane == 0) {
            g_S[(size_t)b * NN + q0 + 0] = sum0;
            g_S[(size_t)b * NN + q0 + 1] = sum1;
            g_S[(size_t)b * NN + q0 + 2] = sum2;
            g_S[(size_t)b * NN + q0 + 3] = sum3;
        }
    }
}

// ---------------- K4: O[p,v] = (1/S[p]) * sum_m E[p,m] V[m,v] ----------------
// 128x128 CTA tile, k-tile 32, 8x8 per-thread microtile.
__global__ __launch_bounds__(256) void k_gemm_o() {
    __shared__ __align__(16) float Es[32 * 132];  // [k][p]
    __shared__ __align__(16) float Vs[32 * 132];  // [k][v]
    int b = blockIdx.x, pt = blockIdx.y, tid = threadIdx.x;
    int r8 = (tid >> 4) << 3, c8 = (tid & 15) << 3;
    float acc[8][8];
#pragma unroll
    for (int i = 0; i < 8; ++i)
#pragma unroll
        for (int j = 0; j < 8; ++j) acc[i][j] = 0.f;
    const float* Ebase = g_E + ((size_t)b * NN + pt * 128) * MM;
    const float* Vbase = g_V + (size_t)b * MM * DV;
    for (int kt = 0; kt < 32; ++kt) {
        for (int f = tid; f < 1024; f += 256) {
            int pr = f >> 3, kc = (f & 7) * 4;
            float4 v = *(const float4*)(Ebase + (size_t)pr * MM + kt * 32 + kc);
            Es[(kc + 0) * 132 + pr] = v.x;
            Es[(kc + 1) * 132 + pr] = v.y;
            Es[(kc + 2) * 132 + pr] = v.z;
            Es[(kc + 3) * 132 + pr] = v.w;
        }
        for (int f = tid; f < 1024; f += 256) {
            int kr = f >> 5, vc = (f & 31) * 4;
            *(float4*)(Vs + kr * 132 + vc) =
                *(const float4*)(Vbase + (size_t)(kt * 32 + kr) * DV + vc);
        }
        __syncthreads();
#pragma unroll
        for (int k = 0; k < 32; ++k) {
            float a[8], bb[8];
            *(float4*)(a + 0) = *(const float4*)(Es + k * 132 + r8);
            *(float4*)(a + 4) = *(const float4*)(Es + k * 132 + r8 + 4);
            *(float4*)(bb + 0) = *(const float4*)(Vs + k * 132 + c8);
            *(float4*)(bb + 4) = *(const float4*)(Vs + k * 132 + c8 + 4);
#pragma unroll
            for (int i = 0; i < 8; ++i)
#pragma unroll
                for (int j = 0; j < 8; ++j) acc[i][j] += a[i] * bb[j];
        }
        __syncthreads();
    }
#pragma unroll
    for (int i = 0; i < 8; ++i) {
        int p = pt * 128 + r8 + i;
        float inv = 1.0f / g_S[(size_t)b * NN + p];
        float* orow = g_O + ((size_t)b * NN + p) * DV + c8;
        *(float4*)(orow + 0) = make_float4(acc[i][0] * inv, acc[i][1] * inv,
                                           acc[i][2] * inv, acc[i][3] * inv);
        *(float4*)(orow + 4) = make_float4(acc[i][4] * inv, acc[i][5] * inv,
                                           acc[i][6] * inv, acc[i][7] * inv);
    }
}

// ---------------- K5: out[b,c,p] = gamma * sum_v Wo[c,v] O[b,p,v] + x[b,c,p] ----------------
__global__ __launch_bounds__(256) void k_out(const float* __restrict__ x,
                                             const float* __restrict__ Wo,
                                             const float* __restrict__ gptr,
                                             float* __restrict__ out) {
    __shared__ __align__(16) float Ws[32 * 132];  // [v][c]
    __shared__ __align__(16) float Os[32 * 132];  // [v][p]
    int b = blockIdx.x, pt = blockIdx.y, ch = blockIdx.z, tid = threadIdx.x;
    int r8 = (tid >> 4) << 3, c8 = (tid & 15) << 3;
    float acc[8][8];
#pragma unroll
    for (int i = 0; i < 8; ++i)
#pragma unroll
        for (int j = 0; j < 8; ++j) acc[i][j] = 0.f;
    const float* Obase = g_O + ((size_t)b * NN + pt * 128) * DV;
    const float* Wbase = Wo + (size_t)ch * 128 * DV;
    for (int kt = 0; kt < 4; ++kt) {
        for (int f = tid; f < 1024; f += 256) {
            int cr = f >> 3, vc = (f & 7) * 4;
            float4 v = *(const float4*)(Wbase + (size_t)cr * DV + kt * 32 + vc);
            Ws[(vc + 0) * 132 + cr] = v.x;
            Ws[(vc + 1) * 132 + cr] = v.y;
            Ws[(vc + 2) * 132 + cr] = v.z;
            Ws[(vc + 3) * 132 + cr] = v.w;
        }
        for (int f = tid; f < 1024; f += 256) {
            int pr = f >> 3, vc = (f & 7) * 4;
            float4 v = *(const float4*)(Obase + (size_t)pr * DV + kt * 32 + vc);
            Os[(vc + 0) * 132 + pr] = v.x;
            Os[(vc + 1) * 132 + pr] = v.y;
            Os[(vc + 2) * 132 + pr] = v.z;
            Os[(vc + 3) * 132 + pr] = v.w;
        }
        __syncthreads();
#pragma unroll
        for (int k = 0; k < 32; ++k) {
            float a[8], bb[8];
            *(float4*)(a + 0) = *(const float4*)(Ws + k * 132 + r8);
            *(float4*)(a + 4) = *(const float4*)(Ws + k * 132 + r8 + 4);
            *(float4*)(bb + 0) = *(const float4*)(Os + k * 132 + c8);
            *(float4*)(bb + 4) = *(const float4*)(Os + k * 132 + c8 + 4);
#pragma unroll
            for (int i = 0; i < 8; ++i)
#pragma unroll
                for (int j = 0; j < 8; ++j) acc[i][j] += a[i] * bb[j];
        }
        __syncthreads();
    }
    float gm = *gptr;
#pragma unroll
    for (int i = 0; i < 8; ++i) {
        int c = ch * 128 + r8 + i;
        size_t row = ((size_t)b * CC + c) * NN + pt * 128 + c8;
        float4 x1 = *(const float4*)(x + row);
        float4 x2 = *(const float4*)(x + row + 4);
        float4 o1 = make_float4(gm * acc[i][0] + x1.x, gm * acc[i][1] + x1.y,
                                gm * acc[i][2] + x1.z, gm * acc[i][3] + x1.w);
        float4 o2 = make_float4(gm * acc[i][4] + x2.x, gm * acc[i][5] + x2.y,
                                gm * acc[i][6] + x2.z, gm * acc[i][7] + x2.w);
        *(float4*)(out + row) = o1;
        *(float4*)(out + row + 4) = o2;
    }
}

// ---------------- launch ----------------
extern "C" void kernel_launch(void* const* d_in, const int* in_sizes, int n_in,
                              void* d_out, int out_size) {
    const float* x     = (const float*)d_in[0];
    const float* Wq    = (const float*)d_in[1];
    const float* Wk    = (const float*)d_in[2];
    const float* Wv    = (const float*)d_in[3];
    const float* Wo    = (const float*)d_in[4];
    const float* gamma = (const float*)d_in[5];
    float* out = (float*)d_out;

    k_proj_q<<<dim3(BB, NN / 256), 256>>>(x, Wq);
    k_proj_kv<<<dim3(BB, MM / 256, 5), 256>>>(x, Wk, Wv);
    k_attn<<<dim3(BB, NN / 64), 256>>>();
    k_gemm_o<<<dim3(BB, NN / 128), 256>>>();
    k_out<<<dim3(BB, NN / 128, 2), 256>>>(x, Wo, gamma, out);
}

// round 4
// speedup vs baseline: 1.5529x; 1.5529x over previous
#include <cuda_runtime.h>
#include <math.h>
#include <stdint.h>

#define BB 8
#define CC 256
#define HH_ 64
#define WW_ 64
#define NN 4096   // H*W
#define MM 1024   // pooled
#define DD 32     // C/8
#define DV 128    // C/2

// ---------------- scratch (static device globals; allocation-free) ----------------
__device__ float g_Q[BB * NN * DD];    // [b][p][dd]
__device__ float g_K[BB * MM * DD];    // [b][mp][dd]
__device__ float g_Vt[BB * DV * MM];   // [b][v][m]  (transposed: B operand is [n][k])
__device__ float g_E[BB * NN * MM];    // exp(scores)
__device__ float g_S[BB * NN];         // row sums
__device__ float g_O[BB * NN * DV];    // [b][p][v]

__device__ __forceinline__ uint32_t f2tf32(float f) {
    uint32_t r;
    asm("cvt.rna.tf32.f32 %0, %1;" : "=r"(r) : "f"(f));
    return r;
}

// ---------------- K1: Q projection ----------------
__global__ __launch_bounds__(256) void k_proj_q(const float* __restrict__ x,
                                                const float* __restrict__ Wq) {
    __shared__ __align__(16) float wt[CC * DD];
    int b = blockIdx.x, pt = blockIdx.y, tid = threadIdx.x;
    for (int i = tid; i < DD * CC; i += 256) {
        int dd = i >> 8, c = i & 255;
        wt[c * DD + dd] = Wq[i];
    }
    __syncthreads();
    int p = pt * 256 + tid;
    const float* xp = x + (size_t)b * CC * NN + p;
    float acc[DD];
#pragma unroll
    for (int i = 0; i < DD; ++i) acc[i] = 0.f;
#pragma unroll 4
    for (int c = 0; c < CC; ++c) {
        float xv = xp[(size_t)c * NN];
        const float4* w4 = (const float4*)(wt + c * DD);
#pragma unroll
        for (int j = 0; j < 8; ++j) {
            float4 w = w4[j];
            acc[4 * j + 0] += w.x * xv;
            acc[4 * j + 1] += w.y * xv;
            acc[4 * j + 2] += w.z * xv;
            acc[4 * j + 3] += w.w * xv;
        }
    }
    float4* qo = (float4*)(g_Q + ((size_t)b * NN + p) * DD);
#pragma unroll
    for (int j = 0; j < 8; ++j)
        qo[j] = make_float4(acc[4 * j], acc[4 * j + 1], acc[4 * j + 2], acc[4 * j + 3]);
}

// ---------------- K2: pooled K/V projections (max over 2x2) ----------------
__global__ __launch_bounds__(256) void k_proj_kv(const float* __restrict__ x,
                                                 const float* __restrict__ Wk,
                                                 const float* __restrict__ Wv) {
    __shared__ __align__(16) float wt[CC * DD];
    int b = blockIdx.x, mt = blockIdx.y, g = blockIdx.z, tid = threadIdx.x;
    const float* Wsrc = (g == 0) ? Wk : (Wv + (size_t)(g - 1) * DD * CC);
    for (int i = tid; i < DD * CC; i += 256) {
        int dd = i >> 8, c = i & 255;
        wt[c * DD + dd] = Wsrc[i];
    }
    __syncthreads();
    int mp = mt * 256 + tid;
    int hh = mp >> 5, ww = mp & 31;
    const float* xb = x + (size_t)b * CC * NN;
    float acc[DD];
#pragma unroll
    for (int i = 0; i < DD; ++i) acc[i] = -3.4e38f;
    for (int j = 0; j < 4; ++j) {
        int p = (hh * 2 + (j >> 1)) * WW_ + ww * 2 + (j & 1);
        float s[DD];
#pragma unroll
        for (int i = 0; i < DD; ++i) s[i] = 0.f;
#pragma unroll 2
        for (int c = 0; c < CC; ++c) {
            float xv = xb[(size_t)c * NN + p];
            const float4* w4 = (const float4*)(wt + c * DD);
#pragma unroll
            for (int jj = 0; jj < 8; ++jj) {
                float4 w = w4[jj];
                s[4 * jj + 0] += w.x * xv;
                s[4 * jj + 1] += w.y * xv;
                s[4 * jj + 2] += w.z * xv;
                s[4 * jj + 3] += w.w * xv;
            }
        }
#pragma unroll
        for (int i = 0; i < DD; ++i) acc[i] = fmaxf(acc[i], s[i]);
    }
    if (g == 0) {
        float4* d4 = (float4*)(g_K + ((size_t)b * MM + mp) * DD);
#pragma unroll
        for (int j = 0; j < 8; ++j)
            d4[j] = make_float4(acc[4 * j], acc[4 * j + 1], acc[4 * j + 2], acc[4 * j + 3]);
    } else {
        int v0 = (g - 1) * 32;
#pragma unroll
        for (int i = 0; i < DD; ++i)
            g_Vt[((size_t)b * DV + v0 + i) * MM + mp] = acc[i];  // coalesced over mp
    }
}

// ---------------- K3: scores + exp + row sums (fp32 SIMT) ----------------
__global__ __launch_bounds__(256) void k_attn() {
    __shared__ __align__(16) float ksh[DD * 129];
    int b = blockIdx.x, qt = blockIdx.y, tid = threadIdx.x;
    int warp = tid >> 5, lane = tid & 31;
    for (int pass = 0; pass < 2; ++pass) {
        int q0 = qt * 64 + pass * 32 + warp * 4;
        float qr[4][DD];
#pragma unroll
        for (int qq = 0; qq < 4; ++qq) {
            const float4* qp = (const float4*)(g_Q + ((size_t)b * NN + q0 + qq) * DD);
#pragma unroll
            for (int j = 0; j < 8; ++j) {
                float4 v = qp[j];
                qr[qq][4 * j + 0] = v.x;
                qr[qq][4 * j + 1] = v.y;
                qr[qq][4 * j + 2] = v.z;
                qr[qq][4 * j + 3] = v.w;
            }
        }
        float sum0 = 0.f, sum1 = 0.f, sum2 = 0.f, sum3 = 0.f;
        size_t e0 = ((size_t)b * NN + q0) * MM;
        for (int mc = 0; mc < 8; ++mc) {
            __syncthreads();
            const float4* src = (const float4*)(g_K + ((size_t)b * MM + mc * 128) * DD);
#pragma unroll
            for (int r = 0; r < 4; ++r) {
                int fi = r * 256 + tid;
                float4 v = src[fi];
                int ml = fi >> 3, c0 = (fi & 7) * 4;
                ksh[(c0 + 0) * 129 + ml] = v.x;
                ksh[(c0 + 1) * 129 + ml] = v.y;
                ksh[(c0 + 2) * 129 + ml] = v.z;
                ksh[(c0 + 3) * 129 + ml] = v.w;
            }
            __syncthreads();
#pragma unroll
            for (int mi = 0; mi < 4; ++mi) {
                int ml = mi * 32 + lane;
                float s0 = 0.f, s1 = 0.f, s2 = 0.f, s3 = 0.f;
#pragma unroll
                for (int c = 0; c < DD; ++c) {
                    float kv = ksh[c * 129 + ml];
                    s0 += qr[0][c] * kv;
                    s1 += qr[1][c] * kv;
                    s2 += qr[2][c] * kv;
                    s3 += qr[3][c] * kv;
                }
                float v0 = __expf(s0), v1 = __expf(s1), v2 = __expf(s2), v3 = __expf(s3);
                sum0 += v0; sum1 += v1; sum2 += v2; sum3 += v3;
                int mg = mc * 128 + ml;
                g_E[e0 + mg] = v0;
                g_E[e0 + (size_t)MM + mg] = v1;
                g_E[e0 + (size_t)2 * MM + mg] = v2;
                g_E[e0 + (size_t)3 * MM + mg] = v3;
            }
        }
#pragma unroll
        for (int o = 16; o > 0; o >>= 1) {
            sum0 += __shfl_xor_sync(0xffffffffu, sum0, o);
            sum1 += __shfl_xor_sync(0xffffffffu, sum1, o);
            sum2 += __shfl_xor_sync(0xffffffffu, sum2, o);
            sum3 += __shfl_xor_sync(0xffffffffu, sum3, o);
        }
        if (lane == 0) {
            g_S[(size_t)b * NN + q0 + 0] = sum0;
            g_S[(size_t)b * NN + q0 + 1] = sum1;
            g_S[(size_t)b * NN + q0 + 2] = sum2;
            g_S[(size_t)b * NN + q0 + 3] = sum3;
        }
    }
}

// ============ tf32 mma.sync warp-tile GEMM core ============
// D[128][128] tile: 8 warps (4 M-blocks of 32 x 2 N-blocks of 64).
// Warp: 2 m16-tiles x 8 n8-tiles, K in chunks of 32 (4 k8-steps).
// smem tiles [128][36] (stride-36 pad: fragment loads bank-conflict-free).
#define TS 36

__device__ __forceinline__ void mma_tf32(float* d, const uint32_t* a, uint32_t b0, uint32_t b1) {
    asm volatile(
        "mma.sync.aligned.m16n8k8.row.col.f32.tf32.tf32.f32 "
        "{%0,%1,%2,%3}, {%4,%5,%6,%7}, {%8,%9}, {%0,%1,%2,%3};"
        : "+f"(d[0]), "+f"(d[1]), "+f"(d[2]), "+f"(d[3])
        : "r"(a[0]), "r"(a[1]), "r"(a[2]), "r"(a[3]), "r"(b0), "r"(b1));
}

// ---------------- K4: O = (E · Vt) / S  via tf32 mma ----------------
__global__ __launch_bounds__(256) void k_gemm_o_mma() {
    __shared__ __align__(16) uint32_t As[128 * TS];
    __shared__ __align__(16) uint32_t Bs[128 * TS];
    int b = blockIdx.x, pt = blockIdx.y, tid = threadIdx.x;
    int warp = tid >> 5, lane = tid & 31;
    int g = lane >> 2, t = lane & 3;
    int wm = warp & 3, wn = warp >> 2;
    float d[2][8][4];
#pragma unroll
    for (int i = 0; i < 2; ++i)
#pragma unroll
        for (int j = 0; j < 8; ++j)
#pragma unroll
            for (int k = 0; k < 4; ++k) d[i][j][k] = 0.f;

    const float* Ebase = g_E + ((size_t)b * NN + pt * 128) * MM;
    const float* Vtbase = g_Vt + (size_t)b * DV * MM;

    for (int kt = 0; kt < 32; ++kt) {
#pragma unroll
        for (int it = 0; it < 4; ++it) {
            int f = it * 256 + tid;
            int row = f >> 3, c4 = (f & 7) * 4;
            float4 e4 = *(const float4*)(Ebase + (size_t)row * MM + kt * 32 + c4);
            uint4 ue = make_uint4(f2tf32(e4.x), f2tf32(e4.y), f2tf32(e4.z), f2tf32(e4.w));
            *(uint4*)(As + row * TS + c4) = ue;
            float4 v4 = *(const float4*)(Vtbase + (size_t)row * MM + kt * 32 + c4);
            uint4 uv = make_uint4(f2tf32(v4.x), f2tf32(v4.y), f2tf32(v4.z), f2tf32(v4.w));
            *(uint4*)(Bs + row * TS + c4) = uv;
        }
        __syncthreads();
#pragma unroll
        for (int kk = 0; kk < 32; kk += 8) {
            uint32_t a[2][4];
#pragma unroll
            for (int mt = 0; mt < 2; ++mt) {
                const uint32_t* ap = As + (wm * 32 + mt * 16 + g) * TS + kk + t;
                a[mt][0] = ap[0];
                a[mt][1] = ap[8 * TS];
                a[mt][2] = ap[4];
                a[mt][3] = ap[8 * TS + 4];
            }
#pragma unroll
            for (int nt = 0; nt < 8; ++nt) {
                const uint32_t* bp = Bs + (wn * 64 + nt * 8 + g) * TS + kk + t;
                uint32_t b0 = bp[0], b1 = bp[4];
                mma_tf32(d[0][nt], a[0], b0, b1);
                mma_tf32(d[1][nt], a[1], b0, b1);
            }
        }
        __syncthreads();
    }
#pragma unroll
    for (int mt = 0; mt < 2; ++mt) {
        int p0 = pt * 128 + wm * 32 + mt * 16 + g;
        float inv0 = 1.0f / g_S[(size_t)b * NN + p0];
        float inv1 = 1.0f / g_S[(size_t)b * NN + p0 + 8];
        float* o0 = g_O + ((size_t)b * NN + p0) * DV;
        float* o1 = g_O + ((size_t)b * NN + p0 + 8) * DV;
#pragma unroll
        for (int nt = 0; nt < 8; ++nt) {
            int col = wn * 64 + nt * 8 + 2 * t;
            *(float2*)(o0 + col) = make_float2(d[mt][nt][0] * inv0, d[mt][nt][1] * inv0);
            *(float2*)(o1 + col) = make_float2(d[mt][nt][2] * inv1, d[mt][nt][3] * inv1);
        }
    }
}

// ---------------- K5: out = gamma * Wo·O^T + x  via tf32 mma ----------------
__global__ __launch_bounds__(256) void k_out_mma(const float* __restrict__ x,
                                                 const float* __restrict__ Wo,
                                                 const float* __restrict__ gptr,
                                                 float* __restrict__ out) {
    __shared__ __align__(16) uint32_t As[128 * TS];
    __shared__ __align__(16) uint32_t Bs[128 * TS];
    int b = blockIdx.x, pt = blockIdx.y, ch = blockIdx.z, tid = threadIdx.x;
    int warp = tid >> 5, lane = tid & 31;
    int g = lane >> 2, t = lane & 3;
    int wm = warp & 3, wn = warp >> 2;
    float d[2][8][4];
#pragma unroll
    for (int i = 0; i < 2; ++i)
#pragma unroll
        for (int j = 0; j < 8; ++j)
#pragma unroll
            for (int k = 0; k < 4; ++k) d[i][j][k] = 0.f;

    const float* Wbase = Wo + (size_t)ch * 128 * DV;
    const float* Obase = g_O + ((size_t)b * NN + pt * 128) * DV;

    for (int kt = 0; kt < 4; ++kt) {
#pragma unroll
        for (int it = 0; it < 4; ++it) {
            int f = it * 256 + tid;
            int row = f >> 3, c4 = (f & 7) * 4;
            float4 w4 = *(const float4*)(Wbase + (size_t)row * DV + kt * 32 + c4);
            uint4 uw = make_uint4(f2tf32(w4.x), f2tf32(w4.y), f2tf32(w4.z), f2tf32(w4.w));
            *(uint4*)(As + row * TS + c4) = uw;
            float4 o4 = *(const float4*)(Obase + (size_t)row * DV + kt * 32 + c4);
            uint4 uo = make_uint4(f2tf32(o4.x), f2tf32(o4.y), f2tf32(o4.z), f2tf32(o4.w));
            *(uint4*)(Bs + row * TS + c4) = uo;
        }
        __syncthreads();
#pragma unroll
        for (int kk = 0; kk < 32; kk += 8) {
            uint32_t a[2][4];
#pragma unroll
            for (int mt = 0; mt < 2; ++mt) {
                const uint32_t* ap = As + (wm * 32 + mt * 16 + g) * TS + kk + t;
                a[mt][0] = ap[0];
                a[mt][1] = ap[8 * TS];
                a[mt][2] = ap[4];
                a[mt][3] = ap[8 * TS + 4];
            }
#pragma unroll
            for (int nt = 0; nt < 8; ++nt) {
                const uint32_t* bp = Bs + (wn * 64 + nt * 8 + g) * TS + kk + t;
                uint32_t b0 = bp[0], b1 = bp[4];
                mma_tf32(d[0][nt], a[0], b0, b1);
                mma_tf32(d[1][nt], a[1], b0, b1);
            }
        }
        __syncthreads();
    }
    float gm = *gptr;
#pragma unroll
    for (int mt = 0; mt < 2; ++mt) {
        int c0 = ch * 128 + wm * 32 + mt * 16 + g;
        size_t r0 = ((size_t)b * CC + c0) * NN + pt * 128;
        size_t r1 = ((size_t)b * CC + c0 + 8) * NN + pt * 128;
#pragma unroll
        for (int nt = 0; nt < 8; ++nt) {
            int col = wn * 64 + nt * 8 + 2 * t;
            float2 x0 = *(const float2*)(x + r0 + col);
            float2 x1 = *(const float2*)(x + r1 + col);
            *(float2*)(out + r0 + col) =
                make_float2(fmaf(gm, d[mt][nt][0], x0.x), fmaf(gm, d[mt][nt][1], x0.y));
            *(float2*)(out + r1 + col) =
                make_float2(fmaf(gm, d[mt][nt][2], x1.x), fmaf(gm, d[mt][nt][3], x1.y));
        }
    }
}

// ---------------- launch ----------------
extern "C" void kernel_launch(void* const* d_in, const int* in_sizes, int n_in,
                              void* d_out, int out_size) {
    const float* x     = (const float*)d_in[0];
    const float* Wq    = (const float*)d_in[1];
    const float* Wk    = (const float*)d_in[2];
    const float* Wv    = (const float*)d_in[3];
    const float* Wo    = (const float*)d_in[4];
    const float* gamma = (const float*)d_in[5];
    float* out = (float*)d_out;

    k_proj_q<<<dim3(BB, NN / 256), 256>>>(x, Wq);
    k_proj_kv<<<dim3(BB, MM / 256, 5), 256>>>(x, Wk, Wv);
    k_attn<<<dim3(BB, NN / 64), 256>>>();
    k_gemm_o_mma<<<dim3(BB, NN / 128), 256>>>();
    k_out_mma<<<dim3(BB, NN / 128, CC / 128), 256>>>(x, Wo, gamma, out);
}

// round 5
// speedup vs baseline: 2.1449x; 1.3813x over previous
#include <cuda_runtime.h>
#include <cuda_bf16.h>
#include <math.h>
#include <stdint.h>

#define BB 8
#define CC 256
#define HH_ 64
#define WW_ 64
#define NN 4096   // H*W
#define MM 1024   // pooled
#define DD 32     // C/8
#define DV 128    // C/2

// ---------------- scratch (static device globals; allocation-free) ----------------
__device__ float g_Q[BB * NN * DD];    // [b][p][dd]
__device__ float g_K[BB * MM * DD];    // [b][mp][dd]
__device__ float g_Vt[BB * DV * MM];   // [b][v][m]
__device__ float g_E[BB * NN * MM];    // exp(scores)
__device__ float g_S[BB * NN];         // row sums
__device__ float g_O[BB * NN * DV];    // [b][p][v]

__device__ __forceinline__ uint32_t f2tf32(float f) {
    uint32_t r;
    asm("cvt.rna.tf32.f32 %0, %1;" : "=r"(r) : "f"(f));
    return r;
}

// pack two floats into bf16x2 hi-word / lo-word split halves
__device__ __forceinline__ void bf16_split2(float v0, float v1, uint32_t& hi, uint32_t& lo) {
    __nv_bfloat16 h0 = __float2bfloat16(v0);
    __nv_bfloat16 h1 = __float2bfloat16(v1);
    __nv_bfloat16 l0 = __float2bfloat16(v0 - __bfloat162float(h0));
    __nv_bfloat16 l1 = __float2bfloat16(v1 - __bfloat162float(h1));
    hi = ((uint32_t)__bfloat16_as_ushort(h1) << 16) | (uint32_t)__bfloat16_as_ushort(h0);
    lo = ((uint32_t)__bfloat16_as_ushort(l1) << 16) | (uint32_t)__bfloat16_as_ushort(l0);
}

__device__ __forceinline__ void mma_bf16(float* d, const uint32_t* a, uint32_t b0, uint32_t b1) {
    asm volatile(
        "mma.sync.aligned.m16n8k16.row.col.f32.bf16.bf16.f32 "
        "{%0,%1,%2,%3}, {%4,%5,%6,%7}, {%8,%9}, {%0,%1,%2,%3};"
        : "+f"(d[0]), "+f"(d[1]), "+f"(d[2]), "+f"(d[3])
        : "r"(a[0]), "r"(a[1]), "r"(a[2]), "r"(a[3]), "r"(b0), "r"(b1));
}

__device__ __forceinline__ void mma_tf32(float* d, const uint32_t* a, uint32_t b0, uint32_t b1) {
    asm volatile(
        "mma.sync.aligned.m16n8k8.row.col.f32.tf32.tf32.f32 "
        "{%0,%1,%2,%3}, {%4,%5,%6,%7}, {%8,%9}, {%0,%1,%2,%3};"
        : "+f"(d[0]), "+f"(d[1]), "+f"(d[2]), "+f"(d[3])
        : "r"(a[0]), "r"(a[1]), "r"(a[2]), "r"(a[3]), "r"(b0), "r"(b1));
}

// ================= K1: fused Q/K/V projection + 2x2 maxpool =================
// CTA: [192 Y-rows (Wq 0..31 | Wk 32..63 | Wv 64..191)] x [128 pixels], K=256.
// 12 warps: wm = warp>>1 (6 m-blocks of 32), wn = warp&1 (2 n-blocks of 64).
// bf16 split 3-mma (hh + hl + lh) for near-fp32 accuracy.
// p-tile 128 = h rows {2*pt, 2*pt+1} -> 2x2 pooling fully inside CTA.
#define PT 12   // words per row in bf16 tiles (8 data + 4 pad) -> conflict-free frags

__global__ __launch_bounds__(384) void k_proj_fused(const float* __restrict__ x,
                                                    const float* __restrict__ Wq,
                                                    const float* __restrict__ Wk,
                                                    const float* __restrict__ Wv) {
    __shared__ uint32_t buf[192 * PT * 2 + 128 * PT * 2];  // 30.7 KB, reused as PB at end
    uint32_t* Ah = buf;
    uint32_t* Al = Ah + 192 * PT;
    uint32_t* Bh = Al + 192 * PT;
    uint32_t* Bl = Bh + 128 * PT;
    float* PB = (float*)buf;  // [160][33] pooling exchange (aliases tiles after loop)

    int b = blockIdx.x, pt = blockIdx.y, tid = threadIdx.x;
    int warp = tid >> 5, lane = tid & 31, g = lane >> 2, t = lane & 3;
    int wm = warp >> 1, wn = warp & 1;

    float d[2][8][4];
#pragma unroll
    for (int i = 0; i < 2; ++i)
#pragma unroll
        for (int j = 0; j < 8; ++j)
#pragma unroll
            for (int k = 0; k < 4; ++k) d[i][j][k] = 0.f;

    const float* xb = x + (size_t)b * CC * NN + pt * 128;

    for (int kt = 0; kt < 16; ++kt) {
        int k0 = kt * 16;
        // load A chunk: rows 0..191, 16 k-values -> 8 packed words (+ split)
        for (int f = tid; f < 192 * 8; f += 384) {
            int r = f >> 3, c2 = f & 7;
            const float* wr = (r < 32) ? (Wq + (size_t)r * CC)
                              : (r < 64) ? (Wk + (size_t)(r - 32) * CC)
                                         : (Wv + (size_t)(r - 64) * CC);
            float2 wv = *(const float2*)(wr + k0 + 2 * c2);
            uint32_t hi, lo;
            bf16_split2(wv.x, wv.y, hi, lo);
            Ah[r * PT + c2] = hi;
            Al[r * PT + c2] = lo;
        }
        // load B chunk: x[k0..k0+15][p0..p0+127] transposed+packed -> [p][8 words]
        for (int f = tid; f < 128 * 8; f += 384) {
            int p = f & 127, c2 = f >> 7;
            float v0 = xb[(size_t)(k0 + 2 * c2) * NN + p];
            float v1 = xb[(size_t)(k0 + 2 * c2 + 1) * NN + p];
            uint32_t hi, lo;
            bf16_split2(v0, v1, hi, lo);
            Bh[p * PT + c2] = hi;
            Bl[p * PT + c2] = lo;
        }
        __syncthreads();
        uint32_t ah[2][4], al[2][4];
#pragma unroll
        for (int mt = 0; mt < 2; ++mt) {
            int R = wm * 32 + mt * 16;
            ah[mt][0] = Ah[(R + g) * PT + t];
            ah[mt][1] = Ah[(R + g + 8) * PT + t];
            ah[mt][2] = Ah[(R + g) * PT + t + 4];
            ah[mt][3] = Ah[(R + g + 8) * PT + t + 4];
            al[mt][0] = Al[(R + g) * PT + t];
            al[mt][1] = Al[(R + g + 8) * PT + t];
            al[mt][2] = Al[(R + g) * PT + t + 4];
            al[mt][3] = Al[(R + g + 8) * PT + t + 4];
        }
#pragma unroll
        for (int nt = 0; nt < 8; ++nt) {
            int n = wn * 64 + nt * 8 + g;
            uint32_t bh0 = Bh[n * PT + t], bh1 = Bh[n * PT + t + 4];
            uint32_t bl0 = Bl[n * PT + t], bl1 = Bl[n * PT + t + 4];
#pragma unroll
            for (int mt = 0; mt < 2; ++mt) {
                mma_bf16(d[mt][nt], ah[mt], bh0, bh1);  // hi*hi
                mma_bf16(d[mt][nt], ah[mt], bl0, bl1);  // hi*lo
                mma_bf16(d[mt][nt], al[mt], bh0, bh1);  // lo*hi
            }
        }
        __syncthreads();
    }

    // ---------------- epilogue ----------------
    if (wm == 0) {
        // Q rows (0..31): no pooling, store Y directly to g_Q[p][dd]
#pragma unroll
        for (int mt = 0; mt < 2; ++mt) {
            int R0 = mt * 16 + g;
#pragma unroll
            for (int nt = 0; nt < 8; ++nt) {
                int p = pt * 128 + wn * 64 + nt * 8 + 2 * t;
                size_t base0 = ((size_t)b * NN + p) * DD;
                size_t base1 = ((size_t)b * NN + p + 1) * DD;
                g_Q[base0 + R0] = d[mt][nt][0];
                g_Q[base1 + R0] = d[mt][nt][1];
                g_Q[base0 + R0 + 8] = d[mt][nt][2];
                g_Q[base1 + R0 + 8] = d[mt][nt][3];
            }
        }
    } else if (wn == 1) {
        // K/V rows, odd-h half: write col-pair maxima to exchange buffer
#pragma unroll
        for (int mt = 0; mt < 2; ++mt) {
            int R = wm * 32 + mt * 16 + g;
#pragma unroll
            for (int nt = 0; nt < 8; ++nt) {
                int ww = nt * 4 + t;
                PB[(R - 32) * 33 + ww] = fmaxf(d[mt][nt][0], d[mt][nt][1]);
                PB[(R - 24) * 33 + ww] = fmaxf(d[mt][nt][2], d[mt][nt][3]);
            }
        }
    }
    __syncthreads();
    if (wm > 0 && wn == 0) {
        // even-h half: final 2x2 max and store K / Vt
#pragma unroll
        for (int mt = 0; mt < 2; ++mt) {
            int R = wm * 32 + mt * 16 + g;
#pragma unroll
            for (int nt = 0; nt < 8; ++nt) {
                int ww = nt * 4 + t;
                float v0 = fmaxf(fmaxf(d[mt][nt][0], d[mt][nt][1]), PB[(R - 32) * 33 + ww]);
                float v1 = fmaxf(fmaxf(d[mt][nt][2], d[mt][nt][3]), PB[(R - 24) * 33 + ww]);
                int m = pt * 32 + ww;
                if (R < 64) {
                    g_K[((size_t)b * MM + m) * DD + (R - 32)] = v0;
                    g_K[((size_t)b * MM + m) * DD + (R - 24)] = v1;
                } else {
                    g_Vt[((size_t)b * DV + (R - 64)) * MM + m] = v0;
                    g_Vt[((size_t)b * DV + (R - 56)) * MM + m] = v1;
                }
            }
        }
    }
}

// ---------------- K3: scores + exp + row sums (fp32 SIMT) ----------------
__global__ __launch_bounds__(256) void k_attn() {
    __shared__ __align__(16) float ksh[DD * 129];
    int b = blockIdx.x, qt = blockIdx.y, tid = threadIdx.x;
    int warp = tid >> 5, lane = tid & 31;
    for (int pass = 0; pass < 2; ++pass) {
        int q0 = qt * 64 + pass * 32 + warp * 4;
        float qr[4][DD];
#pragma unroll
        for (int qq = 0; qq < 4; ++qq) {
            const float4* qp = (const float4*)(g_Q + ((size_t)b * NN + q0 + qq) * DD);
#pragma unroll
            for (int j = 0; j < 8; ++j) {
                float4 v = qp[j];
                qr[qq][4 * j + 0] = v.x;
                qr[qq][4 * j + 1] = v.y;
                qr[qq][4 * j + 2] = v.z;
                qr[qq][4 * j + 3] = v.w;
            }
        }
        float sum0 = 0.f, sum1 = 0.f, sum2 = 0.f, sum3 = 0.f;
        size_t e0 = ((size_t)b * NN + q0) * MM;
        for (int mc = 0; mc < 8; ++mc) {
            __syncthreads();
            const float4* src = (const float4*)(g_K + ((size_t)b * MM + mc * 128) * DD);
#pragma unroll
            for (int r = 0; r < 4; ++r) {
                int fi = r * 256 + tid;
                float4 v = src[fi];
                int ml = fi >> 3, c0 = (fi & 7) * 4;
                ksh[(c0 + 0) * 129 + ml] = v.x;
                ksh[(c0 + 1) * 129 + ml] = v.y;
                ksh[(c0 + 2) * 129 + ml] = v.z;
                ksh[(c0 + 3) * 129 + ml] = v.w;
            }
            __syncthreads();
#pragma unroll
            for (int mi = 0; mi < 4; ++mi) {
                int ml = mi * 32 + lane;
                float s0 = 0.f, s1 = 0.f, s2 = 0.f, s3 = 0.f;
#pragma unroll
                for (int c = 0; c < DD; ++c) {
                    float kv = ksh[c * 129 + ml];
                    s0 += qr[0][c] * kv;
                    s1 += qr[1][c] * kv;
                    s2 += qr[2][c] * kv;
                    s3 += qr[3][c] * kv;
                }
                float v0 = __expf(s0), v1 = __expf(s1), v2 = __expf(s2), v3 = __expf(s3);
                sum0 += v0; sum1 += v1; sum2 += v2; sum3 += v3;
                int mg = mc * 128 + ml;
                g_E[e0 + mg] = v0;
                g_E[e0 + (size_t)MM + mg] = v1;
                g_E[e0 + (size_t)2 * MM + mg] = v2;
                g_E[e0 + (size_t)3 * MM + mg] = v3;
            }
        }
#pragma unroll
        for (int o = 16; o > 0; o >>= 1) {
            sum0 += __shfl_xor_sync(0xffffffffu, sum0, o);
            sum1 += __shfl_xor_sync(0xffffffffu, sum1, o);
            sum2 += __shfl_xor_sync(0xffffffffu, sum2, o);
            sum3 += __shfl_xor_sync(0xffffffffu, sum3, o);
        }
        if (lane == 0) {
            g_S[(size_t)b * NN + q0 + 0] = sum0;
            g_S[(size_t)b * NN + q0 + 1] = sum1;
            g_S[(size_t)b * NN + q0 + 2] = sum2;
            g_S[(size_t)b * NN + q0 + 3] = sum3;
        }
    }
}

// ============ tf32 mma warp-tile GEMM kernels (unchanged from R4) ============
#define TS 36

__global__ __launch_bounds__(256) void k_gemm_o_mma() {
    __shared__ __align__(16) uint32_t As[128 * TS];
    __shared__ __align__(16) uint32_t Bs[128 * TS];
    int b = blockIdx.x, pt = blockIdx.y, tid = threadIdx.x;
    int warp = tid >> 5, lane = tid & 31;
    int g = lane >> 2, t = lane & 3;
    int wm = warp & 3, wn = warp >> 2;
    float d[2][8][4];
#pragma unroll
    for (int i = 0; i < 2; ++i)
#pragma unroll
        for (int j = 0; j < 8; ++j)
#pragma unroll
            for (int k = 0; k < 4; ++k) d[i][j][k] = 0.f;

    const float* Ebase = g_E + ((size_t)b * NN + pt * 128) * MM;
    const float* Vtbase = g_Vt + (size_t)b * DV * MM;

    for (int kt = 0; kt < 32; ++kt) {
#pragma unroll
        for (int it = 0; it < 4; ++it) {
            int f = it * 256 + tid;
            int row = f >> 3, c4 = (f & 7) * 4;
            float4 e4 = *(const float4*)(Ebase + (size_t)row * MM + kt * 32 + c4);
            uint4 ue = make_uint4(f2tf32(e4.x), f2tf32(e4.y), f2tf32(e4.z), f2tf32(e4.w));
            *(uint4*)(As + row * TS + c4) = ue;
            float4 v4 = *(const float4*)(Vtbase + (size_t)row * MM + kt * 32 + c4);
            uint4 uv = make_uint4(f2tf32(v4.x), f2tf32(v4.y), f2tf32(v4.z), f2tf32(v4.w));
            *(uint4*)(Bs + row * TS + c4) = uv;
        }
        __syncthreads();
#pragma unroll
        for (int kk = 0; kk < 32; kk += 8) {
            uint32_t a[2][4];
#pragma unroll
            for (int mt = 0; mt < 2; ++mt) {
                const uint32_t* ap = As + (wm * 32 + mt * 16 + g) * TS + kk + t;
                a[mt][0] = ap[0];
                a[mt][1] = ap[8 * TS];
                a[mt][2] = ap[4];
                a[mt][3] = ap[8 * TS + 4];
            }
#pragma unroll
            for (int nt = 0; nt < 8; ++nt) {
                const uint32_t* bp = Bs + (wn * 64 + nt * 8 + g) * TS + kk + t;
                uint32_t b0 = bp[0], b1 = bp[4];
                mma_tf32(d[0][nt], a[0], b0, b1);
                mma_tf32(d[1][nt], a[1], b0, b1);
            }
        }
        __syncthreads();
    }
#pragma unroll
    for (int mt = 0; mt < 2; ++mt) {
        int p0 = pt * 128 + wm * 32 + mt * 16 + g;
        float inv0 = 1.0f / g_S[(size_t)b * NN + p0];
        float inv1 = 1.0f / g_S[(size_t)b * NN + p0 + 8];
        float* o0 = g_O + ((size_t)b * NN + p0) * DV;
        float* o1 = g_O + ((size_t)b * NN + p0 + 8) * DV;
#pragma unroll
        for (int nt = 0; nt < 8; ++nt) {
            int col = wn * 64 + nt * 8 + 2 * t;
            *(float2*)(o0 + col) = make_float2(d[mt][nt][0] * inv0, d[mt][nt][1] * inv0);
            *(float2*)(o1 + col) = make_float2(d[mt][nt][2] * inv1, d[mt][nt][3] * inv1);
        }
    }
}

__global__ __launch_bounds__(256) void k_out_mma(const float* __restrict__ x,
                                                 const float* __restrict__ Wo,
                                                 const float* __restrict__ gptr,
                                                 float* __restrict__ out) {
    __shared__ __align__(16) uint32_t As[128 * TS];
    __shared__ __align__(16) uint32_t Bs[128 * TS];
    int b = blockIdx.x, pt = blockIdx.y, ch = blockIdx.z, tid = threadIdx.x;
    int warp = tid >> 5, lane = tid & 31;
    int g = lane >> 2, t = lane & 3;
    int wm = warp & 3, wn = warp >> 2;
    float d[2][8][4];
#pragma unroll
    for (int i = 0; i < 2; ++i)
#pragma unroll
        for (int j = 0; j < 8; ++j)
#pragma unroll
            for (int k = 0; k < 4; ++k) d[i][j][k] = 0.f;

    const float* Wbase = Wo + (size_t)ch * 128 * DV;
    const float* Obase = g_O + ((size_t)b * NN + pt * 128) * DV;

    for (int kt = 0; kt < 4; ++kt) {
#pragma unroll
        for (int it = 0; it < 4; ++it) {
            int f = it * 256 + tid;
            int row = f >> 3, c4 = (f & 7) * 4;
            float4 w4 = *(const float4*)(Wbase + (size_t)row * DV + kt * 32 + c4);
            uint4 uw = make_uint4(f2tf32(w4.x), f2tf32(w4.y), f2tf32(w4.z), f2tf32(w4.w));
            *(uint4*)(As + row * TS + c4) = uw;
            float4 o4 = *(const float4*)(Obase + (size_t)row * DV + kt * 32 + c4);
            uint4 uo = make_uint4(f2tf32(o4.x), f2tf32(o4.y), f2tf32(o4.z), f2tf32(o4.w));
            *(uint4*)(Bs + row * TS + c4) = uo;
        }
        __syncthreads();
#pragma unroll
        for (int kk = 0; kk < 32; kk += 8) {
            uint32_t a[2][4];
#pragma unroll
            for (int mt = 0; mt < 2; ++mt) {
                const uint32_t* ap = As + (wm * 32 + mt * 16 + g) * TS + kk + t;
                a[mt][0] = ap[0];
                a[mt][1] = ap[8 * TS];
                a[mt][2] = ap[4];
                a[mt][3] = ap[8 * TS + 4];
            }
#pragma unroll
            for (int nt = 0; nt < 8; ++nt) {
                const uint32_t* bp = Bs + (wn * 64 + nt * 8 + g) * TS + kk + t;
                uint32_t b0 = bp[0], b1 = bp[4];
                mma_tf32(d[0][nt], a[0], b0, b1);
                mma_tf32(d[1][nt], a[1], b0, b1);
            }
        }
        __syncthreads();
    }
    float gm = *gptr;
#pragma unroll
    for (int mt = 0; mt < 2; ++mt) {
        int c0 = ch * 128 + wm * 32 + mt * 16 + g;
        size_t r0 = ((size_t)b * CC + c0) * NN + pt * 128;
        size_t r1 = ((size_t)b * CC + c0 + 8) * NN + pt * 128;
#pragma unroll
        for (int nt = 0; nt < 8; ++nt) {
            int col = wn * 64 + nt * 8 + 2 * t;
            float2 x0 = *(const float2*)(x + r0 + col);
            float2 x1 = *(const float2*)(x + r1 + col);
            *(float2*)(out + r0 + col) =
                make_float2(fmaf(gm, d[mt][nt][0], x0.x), fmaf(gm, d[mt][nt][1], x0.y));
            *(float2*)(out + r1 + col) =
                make_float2(fmaf(gm, d[mt][nt][2], x1.x), fmaf(gm, d[mt][nt][3], x1.y));
        }
    }
}

// ---------------- launch ----------------
extern "C" void kernel_launch(void* const* d_in, const int* in_sizes, int n_in,
                              void* d_out, int out_size) {
    const float* x     = (const float*)d_in[0];
    const float* Wq    = (const float*)d_in[1];
    const float* Wk    = (const float*)d_in[2];
    const float* Wv    = (const float*)d_in[3];
    const float* Wo    = (const float*)d_in[4];
    const float* gamma = (const float*)d_in[5];
    float* out = (float*)d_out;

    k_proj_fused<<<dim3(BB, NN / 128), 384>>>(x, Wq, Wk, Wv);
    k_attn<<<dim3(BB, NN / 64), 256>>>();
    k_gemm_o_mma<<<dim3(BB, NN / 128), 256>>>();
    k_out_mma<<<dim3(BB, NN / 128, CC / 128), 256>>>(x, Wo, gamma, out);
}

// round 8
// speedup vs baseline: 2.1567x; 1.0055x over previous
#include <cuda_runtime.h>
#include <cuda_bf16.h>
#include <math.h>
#include <stdint.h>

#define BB 8
#define CC 256
#define HH_ 64
#define WW_ 64
#define NN 4096   // H*W
#define MM 1024   // pooled
#define DD 32     // C/8
#define DV 128    // C/2

// ---------------- scratch ----------------
__device__ float g_Q[BB * NN * DD];    // [b][p][dd]
__device__ float g_K[BB * MM * DD];    // [b][mp][dd]
__device__ float g_Vt[BB * DV * MM];   // [b][v][m]
__device__ float g_O[BB * NN * DV];    // [b][p][v]

__device__ __forceinline__ uint32_t f2tf32(float f) {
    uint32_t r;
    asm("cvt.rna.tf32.f32 %0, %1;" : "=r"(r) : "f"(f));
    return r;
}

// pack two floats into bf16x2 hi-word / lo-word split halves (elem0 = low 16 bits)
__device__ __forceinline__ void bf16_split2(float v0, float v1, uint32_t& hi, uint32_t& lo) {
    __nv_bfloat16 h0 = __float2bfloat16(v0);
    __nv_bfloat16 h1 = __float2bfloat16(v1);
    __nv_bfloat16 l0 = __float2bfloat16(v0 - __bfloat162float(h0));
    __nv_bfloat16 l1 = __float2bfloat16(v1 - __bfloat162float(h1));
    hi = ((uint32_t)__bfloat16_as_ushort(h1) << 16) | (uint32_t)__bfloat16_as_ushort(h0);
    lo = ((uint32_t)__bfloat16_as_ushort(l1) << 16) | (uint32_t)__bfloat16_as_ushort(l0);
}

__device__ __forceinline__ void mma_bf16(float* d, const uint32_t* a, uint32_t b0, uint32_t b1) {
    asm volatile(
        "mma.sync.aligned.m16n8k16.row.col.f32.bf16.bf16.f32 "
        "{%0,%1,%2,%3}, {%4,%5,%6,%7}, {%8,%9}, {%0,%1,%2,%3};"
        : "+f"(d[0]), "+f"(d[1]), "+f"(d[2]), "+f"(d[3])
        : "r"(a[0]), "r"(a[1]), "r"(a[2]), "r"(a[3]), "r"(b0), "r"(b1));
}

__device__ __forceinline__ void mma_tf32(float* d, const uint32_t* a, uint32_t b0, uint32_t b1) {
    asm volatile(
        "mma.sync.aligned.m16n8k8.row.col.f32.tf32.tf32.f32 "
        "{%0,%1,%2,%3}, {%4,%5,%6,%7}, {%8,%9}, {%0,%1,%2,%3};"
        : "+f"(d[0]), "+f"(d[1]), "+f"(d[2]), "+f"(d[3])
        : "r"(a[0]), "r"(a[1]), "r"(a[2]), "r"(a[3]), "r"(b0), "r"(b1));
}

// ================= K1: fused Q/K/V projection + 2x2 maxpool (R5-passing) =================
#define PT 12

__global__ __launch_bounds__(384) void k_proj_fused(const float* __restrict__ x,
                                                    const float* __restrict__ Wq,
                                                    const float* __restrict__ Wk,
                                                    const float* __restrict__ Wv) {
    __shared__ uint32_t buf[192 * PT * 2 + 128 * PT * 2];
    uint32_t* Ah = buf;
    uint32_t* Al = Ah + 192 * PT;
    uint32_t* Bh = Al + 192 * PT;
    uint32_t* Bl = Bh + 128 * PT;
    float* PB = (float*)buf;

    int b = blockIdx.x, pt = blockIdx.y, tid = threadIdx.x;
    int warp = tid >> 5, lane = tid & 31, g = lane >> 2, t = lane & 3;
    int wm = warp >> 1, wn = warp & 1;

    float d[2][8][4];
#pragma unroll
    for (int i = 0; i < 2; ++i)
#pragma unroll
        for (int j = 0; j < 8; ++j)
#pragma unroll
            for (int k = 0; k < 4; ++k) d[i][j][k] = 0.f;

    const float* xb = x + (size_t)b * CC * NN + pt * 128;

#pragma unroll 1
    for (int kt = 0; kt < 16; ++kt) {
        int k0 = kt * 16;
        for (int f = tid; f < 192 * 8; f += 384) {
            int r = f >> 3, c2 = f & 7;
            const float* wr = (r < 32) ? (Wq + (size_t)r * CC)
                              : (r < 64) ? (Wk + (size_t)(r - 32) * CC)
                                         : (Wv + (size_t)(r - 64) * CC);
            float2 wv = *(const float2*)(wr + k0 + 2 * c2);
            uint32_t hi, lo;
            bf16_split2(wv.x, wv.y, hi, lo);
            Ah[r * PT + c2] = hi;
            Al[r * PT + c2] = lo;
        }
        for (int f = tid; f < 128 * 8; f += 384) {
            int p = f & 127, c2 = f >> 7;
            float v0 = xb[(size_t)(k0 + 2 * c2) * NN + p];
            float v1 = xb[(size_t)(k0 + 2 * c2 + 1) * NN + p];
            uint32_t hi, lo;
            bf16_split2(v0, v1, hi, lo);
            Bh[p * PT + c2] = hi;
            Bl[p * PT + c2] = lo;
        }
        __syncthreads();
        uint32_t ah[2][4], al[2][4];
#pragma unroll
        for (int mt = 0; mt < 2; ++mt) {
            int R = wm * 32 + mt * 16;
            ah[mt][0] = Ah[(R + g) * PT + t];
            ah[mt][1] = Ah[(R + g + 8) * PT + t];
            ah[mt][2] = Ah[(R + g) * PT + t + 4];
            ah[mt][3] = Ah[(R + g + 8) * PT + t + 4];
            al[mt][0] = Al[(R + g) * PT + t];
            al[mt][1] = Al[(R + g + 8) * PT + t];
            al[mt][2] = Al[(R + g) * PT + t + 4];
            al[mt][3] = Al[(R + g + 8) * PT + t + 4];
        }
#pragma unroll
        for (int nt = 0; nt < 8; ++nt) {
            int n = wn * 64 + nt * 8 + g;
            uint32_t bh0 = Bh[n * PT + t], bh1 = Bh[n * PT + t + 4];
            uint32_t bl0 = Bl[n * PT + t], bl1 = Bl[n * PT + t + 4];
#pragma unroll
            for (int mt = 0; mt < 2; ++mt) {
                mma_bf16(d[mt][nt], ah[mt], bh0, bh1);
                mma_bf16(d[mt][nt], ah[mt], bl0, bl1);
                mma_bf16(d[mt][nt], al[mt], bh0, bh1);
            }
        }
        __syncthreads();
    }

    if (wm == 0) {
#pragma unroll
        for (int mt = 0; mt < 2; ++mt) {
            int R0 = mt * 16 + g;
#pragma unroll
            for (int nt = 0; nt < 8; ++nt) {
                int p = pt * 128 + wn * 64 + nt * 8 + 2 * t;
                size_t base0 = ((size_t)b * NN + p) * DD;
                size_t base1 = ((size_t)b * NN + p + 1) * DD;
                g_Q[base0 + R0] = d[mt][nt][0];
                g_Q[base1 + R0] = d[mt][nt][1];
                g_Q[base0 + R0 + 8] = d[mt][nt][2];
                g_Q[base1 + R0 + 8] = d[mt][nt][3];
            }
        }
    } else if (wn == 1) {
#pragma unroll
        for (int mt = 0; mt < 2; ++mt) {
            int R = wm * 32 + mt * 16 + g;
#pragma unroll
            for (int nt = 0; nt < 8; ++nt) {
                int ww = nt * 4 + t;
                PB[(R - 32) * 33 + ww] = fmaxf(d[mt][nt][0], d[mt][nt][1]);
                PB[(R - 24) * 33 + ww] = fmaxf(d[mt][nt][2], d[mt][nt][3]);
            }
        }
    }
    __syncthreads();
    if (wm > 0 && wn == 0) {
#pragma unroll
        for (int mt = 0; mt < 2; ++mt) {
            int R = wm * 32 + mt * 16 + g;
#pragma unroll
            for (int nt = 0; nt < 8; ++nt) {
                int ww = nt * 4 + t;
                float v0 = fmaxf(fmaxf(d[mt][nt][0], d[mt][nt][1]), PB[(R - 32) * 33 + ww]);
                float v1 = fmaxf(fmaxf(d[mt][nt][2], d[mt][nt][3]), PB[(R - 24) * 33 + ww]);
                int m = pt * 32 + ww;
                if (R < 64) {
                    g_K[((size_t)b * MM + m) * DD + (R - 32)] = v0;
                    g_K[((size_t)b * MM + m) * DD + (R - 24)] = v1;
                } else {
                    g_Vt[((size_t)b * DV + (R - 64)) * MM + m] = v0;
                    g_Vt[((size_t)b * DV + (R - 56)) * MM + m] = v1;
                }
            }
        }
    }
}

// ================= K2: flash attention, dv-split warps, bounded unroll ===========
// CTA: 64 q rows, 8 warps = (wq 0..3: q-group of 16) x (wv 0..1: dv half of 64).
// m loop: 16 chunks of 64 keys (NOT unrolled). Scores duplicated across wv.
#define KP 20   // K smem row stride (words)
#define VP 36   // V smem row stride (words)

__global__ __launch_bounds__(256) void k_flash() {
    __shared__ uint32_t kh[64 * KP], kl[64 * KP];   // K chunk [key][ddpair] hi/lo
    __shared__ uint32_t vh[128 * VP], vl[128 * VP]; // V chunk [dv][keypair] hi/lo

    int b = blockIdx.x, qt = blockIdx.y, tid = threadIdx.x;
    int warp = tid >> 5, lane = tid & 31, g = lane >> 2, t = lane & 3;
    int wq = warp >> 1, wv = warp & 1;
    int q0 = qt * 64 + wq * 16;

    // Q A-fragments (2 k16-chunks over dd=32), bf16 split, kept all kernel
    uint32_t qa_h[2][4], qa_l[2][4];
    {
        const float* Qb = g_Q + ((size_t)b * NN + q0) * DD;
#pragma unroll
        for (int kc = 0; kc < 2; ++kc) {
            float2 v00 = *(const float2*)(Qb + (size_t)g * DD + kc * 16 + 2 * t);
            float2 v10 = *(const float2*)(Qb + (size_t)(g + 8) * DD + kc * 16 + 2 * t);
            float2 v01 = *(const float2*)(Qb + (size_t)g * DD + kc * 16 + 2 * t + 8);
            float2 v11 = *(const float2*)(Qb + (size_t)(g + 8) * DD + kc * 16 + 2 * t + 8);
            bf16_split2(v00.x, v00.y, qa_h[kc][0], qa_l[kc][0]);
            bf16_split2(v10.x, v10.y, qa_h[kc][1], qa_l[kc][1]);
            bf16_split2(v01.x, v01.y, qa_h[kc][2], qa_l[kc][2]);
            bf16_split2(v11.x, v11.y, qa_h[kc][3], qa_l[kc][3]);
        }
    }

    float o[8][4];
#pragma unroll
    for (int i = 0; i < 8; ++i)
#pragma unroll
        for (int j = 0; j < 4; ++j) o[i][j] = 0.f;
    float rs0 = 0.f, rs1 = 0.f;

    const float* Kb = g_K + (size_t)b * MM * DD;
    const float* Vb = g_Vt + (size_t)b * DV * MM;

#pragma unroll 1
    for (int mc = 0; mc < 16; ++mc) {
        int m0 = mc * 64;
        // stage K chunk: 64 keys x 16 dd-pairs (1024 words, 4/thread)
#pragma unroll
        for (int i = 0; i < 4; ++i) {
            int f = i * 256 + tid;
            int key = f >> 4, pr = f & 15;
            float2 kv = *(const float2*)(Kb + (size_t)(m0 + key) * DD + 2 * pr);
            uint32_t hi, lo;
            bf16_split2(kv.x, kv.y, hi, lo);
            kh[key * KP + pr] = hi;
            kl[key * KP + pr] = lo;
        }
        // stage V chunk: 128 dv x 32 key-pairs (4096 words, 16/thread)
#pragma unroll
        for (int i = 0; i < 16; ++i) {
            int f = i * 256 + tid;
            int dv = f >> 5, pr = f & 31;
            float2 vv = *(const float2*)(Vb + (size_t)dv * MM + m0 + 2 * pr);
            uint32_t hi, lo;
            bf16_split2(vv.x, vv.y, hi, lo);
            vh[dv * VP + pr] = hi;
            vl[dv * VP + pr] = lo;
        }
        __syncthreads();

        // ---- scores: S[16 q][64 keys] (duplicated across wv) ----
        float d[8][4];
#pragma unroll
        for (int i = 0; i < 8; ++i)
#pragma unroll
            for (int j = 0; j < 4; ++j) d[i][j] = 0.f;
#pragma unroll
        for (int nt = 0; nt < 8; ++nt) {
            int kr = nt * 8 + g;
#pragma unroll
            for (int kc = 0; kc < 2; ++kc) {
                uint32_t bh0 = kh[kr * KP + kc * 8 + t], bh1 = kh[kr * KP + kc * 8 + t + 4];
                uint32_t bl0 = kl[kr * KP + kc * 8 + t], bl1 = kl[kr * KP + kc * 8 + t + 4];
                mma_bf16(d[nt], qa_h[kc], bh0, bh1);
                mma_bf16(d[nt], qa_h[kc], bl0, bl1);
                mma_bf16(d[nt], qa_l[kc], bh0, bh1);
            }
        }
        // ---- exp + row sums + pack E into A-fragments (in-register) ----
        uint32_t eh[4][4], el[4][4];
#pragma unroll
        for (int nt = 0; nt < 8; ++nt) {
            d[nt][0] = __expf(d[nt][0]);
            d[nt][1] = __expf(d[nt][1]);
            d[nt][2] = __expf(d[nt][2]);
            d[nt][3] = __expf(d[nt][3]);
            rs0 += d[nt][0] + d[nt][1];
            rs1 += d[nt][2] + d[nt][3];
        }
#pragma unroll
        for (int jc = 0; jc < 4; ++jc) {
            bf16_split2(d[2 * jc][0], d[2 * jc][1], eh[jc][0], el[jc][0]);
            bf16_split2(d[2 * jc][2], d[2 * jc][3], eh[jc][1], el[jc][1]);
            bf16_split2(d[2 * jc + 1][0], d[2 * jc + 1][1], eh[jc][2], el[jc][2]);
            bf16_split2(d[2 * jc + 1][2], d[2 * jc + 1][3], eh[jc][3], el[jc][3]);
        }
        // ---- PV: O[16 q][64 dv half] += E[16][64] * V[64][dv half] ----
#pragma unroll
        for (int jc = 0; jc < 4; ++jc) {
#pragma unroll
            for (int nv = 0; nv < 8; ++nv) {
                int vr = wv * 64 + nv * 8 + g;
                uint32_t bh0 = vh[vr * VP + jc * 8 + t], bh1 = vh[vr * VP + jc * 8 + t + 4];
                uint32_t bl0 = vl[vr * VP + jc * 8 + t], bl1 = vl[vr * VP + jc * 8 + t + 4];
                mma_bf16(o[nv], eh[jc], bh0, bh1);
                mma_bf16(o[nv], eh[jc], bl0, bl1);
                mma_bf16(o[nv], el[jc], bh0, bh1);
            }
        }
        __syncthreads();
    }

    // row-sum reduce across t lanes (lane bits 0-1)
    rs0 += __shfl_xor_sync(0xffffffffu, rs0, 1);
    rs0 += __shfl_xor_sync(0xffffffffu, rs0, 2);
    rs1 += __shfl_xor_sync(0xffffffffu, rs1, 1);
    rs1 += __shfl_xor_sync(0xffffffffu, rs1, 2);
    float inv0 = 1.0f / rs0, inv1 = 1.0f / rs1;

    float* o0 = g_O + ((size_t)b * NN + q0 + g) * DV + wv * 64;
    float* o1 = g_O + ((size_t)b * NN + q0 + g + 8) * DV + wv * 64;
#pragma unroll
    for (int nv = 0; nv < 8; ++nv) {
        int col = nv * 8 + 2 * t;
        *(float2*)(o0 + col) = make_float2(o[nv][0] * inv0, o[nv][1] * inv0);
        *(float2*)(o1 + col) = make_float2(o[nv][2] * inv1, o[nv][3] * inv1);
    }
}

// ============ K3: out = gamma * Wo·O^T + x  (tf32 mma, R5-passing) ============
#define TS 36

__global__ __launch_bounds__(256) void k_out_mma(const float* __restrict__ x,
                                                 const float* __restrict__ Wo,
                                                 const float* __restrict__ gptr,
                                                 float* __restrict__ out) {
    __shared__ __align__(16) uint32_t As[128 * TS];
    __shared__ __align__(16) uint32_t Bs[128 * TS];
    int b = blockIdx.x, pt = blockIdx.y, ch = blockIdx.z, tid = threadIdx.x;
    int warp = tid >> 5, lane = tid & 31;
    int g = lane >> 2, t = lane & 3;
    int wm = warp & 3, wn = warp >> 2;
    float d[2][8][4];
#pragma unroll
    for (int i = 0; i < 2; ++i)
#pragma unroll
        for (int j = 0; j < 8; ++j)
#pragma unroll
            for (int k = 0; k < 4; ++k) d[i][j][k] = 0.f;

    const float* Wbase = Wo + (size_t)ch * 128 * DV;
    const float* Obase = g_O + ((size_t)b * NN + pt * 128) * DV;

#pragma unroll 1
    for (int kt = 0; kt < 4; ++kt) {
#pragma unroll
        for (int it = 0; it < 4; ++it) {
            int f = it * 256 + tid;
            int row = f >> 3, c4 = (f & 7) * 4;
            float4 w4 = *(const float4*)(Wbase + (size_t)row * DV + kt * 32 + c4);
            uint4 uw = make_uint4(f2tf32(w4.x), f2tf32(w4.y), f2tf32(w4.z), f2tf32(w4.w));
            *(uint4*)(As + row * TS + c4) = uw;
            float4 o4 = *(const float4*)(Obase + (size_t)row * DV + kt * 32 + c4);
            uint4 uo = make_uint4(f2tf32(o4.x), f2tf32(o4.y), f2tf32(o4.z), f2tf32(o4.w));
            *(uint4*)(Bs + row * TS + c4) = uo;
        }
        __syncthreads();
#pragma unroll
        for (int kk = 0; kk < 32; kk += 8) {
            uint32_t a[2][4];
#pragma unroll
            for (int mt = 0; mt < 2; ++mt) {
                const uint32_t* ap = As + (wm * 32 + mt * 16 + g) * TS + kk + t;
                a[mt][0] = ap[0];
                a[mt][1] = ap[8 * TS];
                a[mt][2] = ap[4];
                a[mt][3] = ap[8 * TS + 4];
            }
#pragma unroll
            for (int nt = 0; nt < 8; ++nt) {
                const uint32_t* bp = Bs + (wn * 64 + nt * 8 + g) * TS + kk + t;
                uint32_t b0 = bp[0], b1 = bp[4];
                mma_tf32(d[0][nt], a[0], b0, b1);
                mma_tf32(d[1][nt], a[1], b0, b1);
            }
        }
        __syncthreads();
    }
    float gm = *gptr;
#pragma unroll
    for (int mt = 0; mt < 2; ++mt) {
        int c0 = ch * 128 + wm * 32 + mt * 16 + g;
        size_t r0 = ((size_t)b * CC + c0) * NN + pt * 128;
        size_t r1 = ((size_t)b * CC + c0 + 8) * NN + pt * 128;
#pragma unroll
        for (int nt = 0; nt < 8; ++nt) {
            int col = wn * 64 + nt * 8 + 2 * t;
            float2 x0 = *(const float2*)(x + r0 + col);
            float2 x1 = *(const float2*)(x + r1 + col);
            *(float2*)(out + r0 + col) =
                make_float2(fmaf(gm, d[mt][nt][0], x0.x), fmaf(gm, d[mt][nt][1], x0.y));
            *(float2*)(out + r1 + col) =
                make_float2(fmaf(gm, d[mt][nt][2], x1.x), fmaf(gm, d[mt][nt][3], x1.y));
        }
    }
}

// ---------------- launch ----------------
extern "C" void kernel_launch(void* const* d_in, const int* in_sizes, int n_in,
                              void* d_out, int out_size) {
    const float* x     = (const float*)d_in[0];
    const float* Wq    = (const float*)d_in[1];
    const float* Wk    = (const float*)d_in[2];
    const float* Wv    = (const float*)d_in[3];
    const float* Wo    = (const float*)d_in[4];
    const float* gamma = (const float*)d_in[5];
    float* out = (float*)d_out;

    k_proj_fused<<<dim3(BB, NN / 128), 384>>>(x, Wq, Wk, Wv);
    k_flash<<<dim3(BB, NN / 64), 256>>>();
    k_out_mma<<<dim3(BB, NN / 128, CC / 128), 256>>>(x, Wo, gamma, out);
}